// round 1
// baseline (speedup 1.0000x reference)
#include <cuda_runtime.h>

// Analytic Clifford collapse of the 14-qubit circuit:
//   |0..0> -H-RY(atan x)-RZ(atan x^2)-  => product state, per-qubit Bloch vector
//   28 CNOT perms                       => GF(2)-linear map Pi (Clifford)
//   U3(w) then <Z_w>                    => <psi| n.sigma |psi> with Pauli strings
// Each output = n_z*prod(Zf over Zmask) + n_x*prod(Xf over Xmask)
//             + n_y*Re(i * prod(per-qubit X/Z/XZ expectations))

#define NQ 14
#define BPB 16                       // batch elements per block
#define TPB (BPB * NQ)               // 224 threads

struct Masks {
    unsigned x[NQ];
    unsigned z[NQ];
};

__global__ __launch_bounds__(TPB)
void qulinear_pauli_kernel(const float* __restrict__ x,
                           const float* __restrict__ u3,
                           float* __restrict__ out,
                           int B, Masks mk)
{
    const int t       = threadIdx.x;
    const int b_local = t / NQ;
    const int w       = t - b_local * NQ;     // qubit / output index
    const int b       = blockIdx.x * BPB + b_local;
    const bool active = (b < B);

    __shared__ float sXf[BPB][NQ];   // <X>  = cos(ry)cos(rz)
    __shared__ float sZf[BPB][NQ];   // <Z>  = -sin(ry)
    __shared__ float sCW[BPB][NQ];   // <XZ> = -i*CW, CW = cos(ry)sin(rz)

    // Phase 1: per-(batch, qubit) Bloch factors. ry=atan(x), rz=atan(x^2):
    //   sin(atan u)=u/sqrt(1+u^2), cos(atan u)=1/sqrt(1+u^2) -> no trig needed.
    if (active) {
        float xv = x[b * NQ + w];
        float x2 = xv * xv;
        float r1 = rsqrtf(1.0f + x2);        // cos(ry)
        float r2 = rsqrtf(1.0f + x2 * x2);   // cos(rz)
        sZf[b_local][w] = -xv * r1;          // -sin(ry)
        sXf[b_local][w] = r1 * r2;           // cos(ry)cos(rz)
        sCW[b_local][w] = x2 * r1 * r2;      // cos(ry)sin(rz)
    }
    __syncthreads();

    if (!active) return;

    // Phase 2: output (b, w).
    // A = U3^dag Z U3 = cos(th) Z - sin(th)cos(lam) X + sin(th)sin(lam) Y
    float th  = u3[w * 3 + 0];
    float lam = u3[w * 3 + 2];
    float sth, cth, sl, cl;
    sincosf(th,  &sth, &cth);
    sincosf(lam, &sl,  &cl);

    const unsigned xmask = mk.x[w];
    const unsigned zmask = mk.z[w];

    float EZ = 1.0f, EX = 1.0f;
    float yre = 1.0f, yim = 0.0f;   // complex accumulator for the Y string

    #pragma unroll
    for (int q = 0; q < NQ; ++q) {
        float Xf = sXf[b_local][q];
        float Zf = sZf[b_local][q];
        float CW = sCW[b_local][q];
        unsigned bit = 1u << (NQ - 1 - q);
        bool xb = (xmask & bit) != 0;
        bool zb = (zmask & bit) != 0;

        if (zb) EZ *= Zf;
        if (xb) EX *= Xf;

        if (xb && zb) {
            // multiply by <XZ> = -i*CW : (re + i*im)*(-i*CW) = CW*im - i*CW*re
            float r = yre, i = yim;
            yre =  CW * i;
            yim = -CW * r;
        } else if (xb) {
            yre *= Xf; yim *= Xf;
        } else if (zb) {
            yre *= Zf; yim *= Zf;
        }
    }
    // Y term = Re( i * (yre + i*yim) ) = -yim
    float result = cth * EZ + (-sth * cl) * EX + (sth * sl) * (-yim);
    out[b * NQ + w] = result;
}

// ---------------------------------------------------------------------------
// Host side: compose the 28 CNOT permutations as a GF(2)-linear map.
// Reference applies state = state[perm] for perms p0..p27 in order, so
// final[i] = initial[p0(p1(...p27(i)...))]; each CNOT perm is a linear
// involution x -> x ^ (tmask * bit_c(x)).
// Xmask[w] = Pi(e_w)   (image of qubit-w basis bit)
// Zmask[w][q] = bit_w(PiInv(e_q))   (row w of Pi^{-1})
// ---------------------------------------------------------------------------
static void compute_masks(Masks* mk)
{
    int ctrl[28], tgt[28];
    int k = 0;
    for (int step = 1; step <= 2; ++step)
        for (int c = 0; c < NQ; ++c) {
            ctrl[k] = c;
            tgt[k]  = (c + step) % NQ;
            ++k;
        }

    auto ap = [&](unsigned v, int kk) -> unsigned {
        unsigned cm = 1u << (NQ - 1 - ctrl[kk]);
        unsigned tm = 1u << (NQ - 1 - tgt[kk]);
        return (v & cm) ? (v ^ tm) : v;
    };

    unsigned picols[NQ], piinvcols[NQ];
    for (int w = 0; w < NQ; ++w) {
        unsigned v = 1u << (NQ - 1 - w);
        for (int kk = 27; kk >= 0; --kk) v = ap(v, kk);   // Pi: p27 innermost
        picols[w] = v;
    }
    for (int q = 0; q < NQ; ++q) {
        unsigned v = 1u << (NQ - 1 - q);
        for (int kk = 0; kk < 28; ++kk) v = ap(v, kk);    // Pi^{-1}
        piinvcols[q] = v;
    }
    for (int w = 0; w < NQ; ++w) {
        mk->x[w] = picols[w];
        unsigned z = 0;
        for (int q = 0; q < NQ; ++q)
            z |= ((piinvcols[q] >> (NQ - 1 - w)) & 1u) << (NQ - 1 - q);
        mk->z[w] = z;
    }
}

extern "C" void kernel_launch(void* const* d_in, const int* in_sizes, int n_in,
                              void* d_out, int out_size)
{
    const float* x  = (const float*)d_in[0];   // [B, 14]
    const float* u3 = (const float*)d_in[1];   // [14, 3]
    float* out = (float*)d_out;                // [B, 14]

    int B = in_sizes[0] / NQ;

    Masks mk;
    compute_masks(&mk);   // pure host arithmetic, capture-safe

    int grid = (B + BPB - 1) / BPB;
    qulinear_pauli_kernel<<<grid, TPB>>>(x, u3, out, B, mk);
}

// round 2
// speedup vs baseline: 1.1884x; 1.1884x over previous
#include <cuda_runtime.h>

// Analytic Clifford collapse of the 14-qubit circuit (see R1):
//   product state per qubit:  <X>=Xf, <Z>=Zf, <XZ>=-i*CW  (CW real >= 0)
//   CNOT layer = GF(2)-linear permutation Pi (host-composed masks)
//   out[b][w] = c0*prod_Z + c1*prod_X + c2*prod_Y
// where prod_Y uses the purely-imaginary <XZ>:  Y-string = (-i)^k * P (P real),
// so the Y term is yc[w]*P with yc in {-1,0,+1}, k = popc(xmask & zmask).

#define NQ  14
#define BPB 16                       // batch rows per block
#define TPB (BPB * NQ)               // 224 threads

struct Masks {
    unsigned x[NQ];
    unsigned z[NQ];
    float    yc[NQ];                 // Y-term sign: +1 (k%4==1), -1 (k%4==3), 0 (k even)
};

__global__ __launch_bounds__(TPB)
void qulinear_pauli_kernel(const float* __restrict__ x,
                           const float* __restrict__ u3,
                           float* __restrict__ out,
                           int B, Masks mk)
{
    const int t       = threadIdx.x;
    const int b_local = t / NQ;
    const int w       = t - b_local * NQ;
    const int b       = blockIdx.x * BPB + b_local;
    const bool active = (b < B);

    __shared__ float4 sF[BPB][NQ];   // {Xf, Zf, CW, 0}
    __shared__ float  sC0[NQ], sC1[NQ], sC2[NQ];

    // Phase 1a: per-(batch,qubit) Bloch factors. ry=atan(x), rz=atan(x^2):
    //   sin(atan u)=u*rsqrt(1+u^2), cos(atan u)=rsqrt(1+u^2) -> no trig.
    if (active) {
        float xv = x[b * NQ + w];
        float x2 = xv * xv;
        float r1 = rsqrtf(1.0f + x2);        // cos(ry)
        float r2 = rsqrtf(1.0f + x2 * x2);   // cos(rz)
        float4 f;
        f.x = r1 * r2;                       // <X>  = cos(ry)cos(rz)
        f.y = -xv * r1;                      // <Z>  = -sin(ry)
        f.z = x2 * r1 * r2;                  // CW (= cos(ry)sin(rz)),  <XZ> = -i*CW
        f.w = 0.0f;
        sF[b_local][w] = f;
    }

    // Phase 1b: per-w measurement coefficients, computed once per block.
    //   U3^dag Z U3 = cos(th) Z - sin(th)cos(lam) X + sin(th)sin(lam) Y
    if (t < NQ) {
        float th  = u3[t * 3 + 0];
        float lam = u3[t * 3 + 2];
        float sth, cth, sl, cl;
        __sincosf(th,  &sth, &cth);
        __sincosf(lam, &sl,  &cl);
        sC0[t] = cth;
        sC1[t] = -sth * cl;
        sC2[t] = sth * sl * mk.yc[t];        // Y sign (or 0) folded in
    }
    __syncthreads();

    if (!active) return;

    const unsigned xm = mk.x[w];
    const unsigned zm = mk.z[w];

    float EZ = 1.0f, EX = 1.0f, PY = 1.0f;

    #pragma unroll
    for (int q = 0; q < NQ; ++q) {
        float4 f = sF[b_local][q];
        const unsigned bit = 1u << (NQ - 1 - q);
        const bool xb = (xm & bit) != 0;
        const bool zb = (zm & bit) != 0;

        EZ *= zb ? f.y : 1.0f;
        EX *= xb ? f.x : 1.0f;
        // Y-string real magnitude: CW where both, Xf where x-only, Zf where z-only
        float pf = xb ? (zb ? f.z : f.x) : (zb ? f.y : 1.0f);
        PY *= pf;
    }

    out[b * NQ + w] = sC0[w] * EZ + sC1[w] * EX + sC2[w] * PY;
}

// ---------------------------------------------------------------------------
// Host: compose the 28 CNOT permutations as a GF(2)-linear map (see R1).
// Runs once at graph capture; parameters are frozen into the graph.
// ---------------------------------------------------------------------------
static void compute_masks(Masks* mk)
{
    int ctrl[28], tgt[28];
    int k = 0;
    for (int step = 1; step <= 2; ++step)
        for (int c = 0; c < NQ; ++c) {
            ctrl[k] = c;
            tgt[k]  = (c + step) % NQ;
            ++k;
        }

    auto ap = [&](unsigned v, int kk) -> unsigned {
        unsigned cm = 1u << (NQ - 1 - ctrl[kk]);
        unsigned tm = 1u << (NQ - 1 - tgt[kk]);
        return (v & cm) ? (v ^ tm) : v;
    };

    unsigned picols[NQ], piinvcols[NQ];
    for (int w = 0; w < NQ; ++w) {
        unsigned v = 1u << (NQ - 1 - w);
        for (int kk = 27; kk >= 0; --kk) v = ap(v, kk);   // Pi (p27 innermost)
        picols[w] = v;
    }
    for (int q = 0; q < NQ; ++q) {
        unsigned v = 1u << (NQ - 1 - q);
        for (int kk = 0; kk < 28; ++kk) v = ap(v, kk);    // Pi^{-1}
        piinvcols[q] = v;
    }
    for (int w = 0; w < NQ; ++w) {
        mk->x[w] = picols[w];
        unsigned z = 0;
        for (int q = 0; q < NQ; ++q)
            z |= ((piinvcols[q] >> (NQ - 1 - w)) & 1u) << (NQ - 1 - q);
        mk->z[w] = z;

        // Y coefficient: k = popc(x&z); -Im((-i)^k) = +1 (k%4==1), -1 (k%4==3), else 0
        unsigned a = mk->x[w] & mk->z[w];
        int pc = 0;
        for (int q = 0; q < NQ; ++q) pc += (a >> q) & 1u;
        mk->yc[w] = (pc % 4 == 1) ? 1.0f : (pc % 4 == 3) ? -1.0f : 0.0f;
    }
}

extern "C" void kernel_launch(void* const* d_in, const int* in_sizes, int n_in,
                              void* d_out, int out_size)
{
    const float* x  = (const float*)d_in[0];   // [B, 14]
    const float* u3 = (const float*)d_in[1];   // [14, 3]
    float* out = (float*)d_out;                // [B, 14]

    int B = in_sizes[0] / NQ;

    Masks mk;
    compute_masks(&mk);

    int grid = (B + BPB - 1) / BPB;
    qulinear_pauli_kernel<<<grid, TPB>>>(x, u3, out, B, mk);
}